// round 4
// baseline (speedup 1.0000x reference)
#include <cuda_runtime.h>
#include <cuda_bf16.h>
#include <stdint.h>

// Problem constants
#define B_FEAT 128
#define U_UNITS 100000
#define K_NBR 500
#define N_RUNS 10
#define N_PAIRS 124750.0
#define T2 64          // pair tile edge
#define NT2 8          // ceil(500/64)
#define NTP2 36        // 8*9/2 lower-tri tile pairs (incl diagonal)
#define TOTAL_BLOCKS (NTP2 * N_RUNS)
#define C4_CHUNK 16    // float4 columns staged per chunk (64 floats)

// Scratch (device globals; no allocation allowed)
__device__ float  g_Y[N_RUNS][K_NBR][B_FEAT];   // normalized centered features
__device__ float2 g_P[N_RUNS][K_NBR];           // gathered positions
__device__ double g_part[TOTAL_BLOCKS][5];      // per-block partial sums
__device__ int    g_done = 0;                   // finalize counter (reset by finalizer)

struct Choice { int v[N_RUNS]; };

// ---------------------------------------------------------------------------
// Kernel 1: gather + center + normalize feature columns; gather positions
// grid (K_NBR, N_RUNS), block 128 (one thread per feature dim)
// ---------------------------------------------------------------------------
__global__ void prep_kernel(const float* __restrict__ feat,
                            const float* __restrict__ pos,
                            const int*   __restrict__ nbh,
                            Choice ch) {
    int u   = blockIdx.x;
    int run = blockIdx.y;
    int f   = threadIdx.x;
    int wid = f >> 5, lane = f & 31;

    int ind = __ldg(&nbh[ch.v[run] * K_NBR + u]);
    float v = __ldg(&feat[f * U_UNITS + ind]);

    __shared__ float ws[4];
    float s = v;
    #pragma unroll
    for (int o = 16; o > 0; o >>= 1) s += __shfl_xor_sync(0xFFFFFFFFu, s, o);
    if (lane == 0) ws[wid] = s;
    __syncthreads();
    float mean = (ws[0] + ws[1] + ws[2] + ws[3]) * (1.0f / B_FEAT);
    __syncthreads();

    float c = v - mean;
    float q = c * c;
    #pragma unroll
    for (int o = 16; o > 0; o >>= 1) q += __shfl_xor_sync(0xFFFFFFFFu, q, o);
    if (lane == 0) ws[wid] = q;
    __syncthreads();
    float inv = rsqrtf(ws[0] + ws[1] + ws[2] + ws[3]);

    g_Y[run][u][f] = c * inv;
    if (f == 0) g_P[run][u] = make_float2(__ldg(&pos[ind * 2]), __ldg(&pos[ind * 2 + 1]));
}

// ---------------------------------------------------------------------------
// Kernel 2: pair sums. 64x64 tiles, 256 threads, 4x4 register micro-tile.
// Feature dim staged in TWO chunks of 64 floats -> static smem ~36KB ->
// 4 blocks/SM resident (reg-capped via __launch_bounds__(256,4)).
// Stride-17 float4 rows keep LDS.128 conflict-free.
// ---------------------------------------------------------------------------
__global__ __launch_bounds__(256, 4) void pair_kernel(float* __restrict__ out) {
    __shared__ float4 Yi[T2][C4_CHUNK + 1];
    __shared__ float4 Yj[T2][C4_CHUNK + 1];
    __shared__ float2 Pi[T2], Pj[T2];
    __shared__ float  wsum[8][5];

    int run = blockIdx.y;
    int t   = blockIdx.x;
    int ti = 0;
    while ((ti + 1) * (ti + 2) / 2 <= t) ti++;
    int tj = t - ti * (ti + 1) / 2;
    int i0 = ti * T2, j0 = tj * T2;

    int tid = threadIdx.x;
    int tx = tid & 15, ty = tid >> 4;

    float acc[4][4] = {};

    #pragma unroll
    for (int chunk = 0; chunk < 2; chunk++) {
        // stage this chunk: each row = 16 float4 = 64 floats
        for (int idx = tid; idx < T2 * C4_CHUNK; idx += 256) {
            int r = idx >> 4, c = idx & 15;
            int gi = i0 + r, gj = j0 + r;
            int gc = chunk * C4_CHUNK + c;
            Yi[r][c] = (gi < K_NBR) ? ((const float4*)g_Y[run][gi])[gc] : make_float4(0, 0, 0, 0);
            Yj[r][c] = (gj < K_NBR) ? ((const float4*)g_Y[run][gj])[gc] : make_float4(0, 0, 0, 0);
        }
        if (chunk == 0) {
            if (tid < T2) {
                Pi[tid] = (i0 + tid < K_NBR) ? g_P[run][i0 + tid] : make_float2(0, 0);
            } else if (tid < 2 * T2) {
                int k = tid - T2;
                Pj[k] = (j0 + k < K_NBR) ? g_P[run][j0 + k] : make_float2(0, 0);
            }
        }
        __syncthreads();

        #pragma unroll
        for (int c = 0; c < C4_CHUNK; c++) {
            float4 af[4], bf[4];
            #pragma unroll
            for (int a = 0; a < 4; a++) af[a] = Yi[ty + 16 * a][c];
            #pragma unroll
            for (int b = 0; b < 4; b++) bf[b] = Yj[tx + 16 * b][c];
            #pragma unroll
            for (int a = 0; a < 4; a++)
                #pragma unroll
                for (int b = 0; b < 4; b++)
                    acc[a][b] += af[a].x * bf[b].x + af[a].y * bf[b].y
                               + af[a].z * bf[b].z + af[a].w * bf[b].w;
        }
        __syncthreads();
    }

    float sr = 0.f, sd = 0.f, srd = 0.f, srr = 0.f, sdd = 0.f;
    #pragma unroll
    for (int a = 0; a < 4; a++) {
        int li = ty + 16 * a, gi = i0 + li;
        float2 pi = Pi[li];
        #pragma unroll
        for (int b = 0; b < 4; b++) {
            int lj = tx + 16 * b, gj = j0 + lj;
            if (gi < K_NBR && gj < K_NBR && gi > gj) {
                float dot = acc[a][b];
                float dx = pi.x - Pj[lj].x;
                float dy = pi.y - Pj[lj].y;
                float ds = 1.0f / (sqrtf(dx * dx + dy * dy) + 1.0f);
                sr  += dot;
                sd  += ds;
                srd += dot * ds;
                srr += dot * dot;
                sdd += ds * ds;
            }
        }
    }

    // block reduce 5 sums
    #pragma unroll
    for (int off = 16; off > 0; off >>= 1) {
        sr  += __shfl_down_sync(0xFFFFFFFFu, sr,  off);
        sd  += __shfl_down_sync(0xFFFFFFFFu, sd,  off);
        srd += __shfl_down_sync(0xFFFFFFFFu, srd, off);
        srr += __shfl_down_sync(0xFFFFFFFFu, srr, off);
        sdd += __shfl_down_sync(0xFFFFFFFFu, sdd, off);
    }
    int wid = tid >> 5, lane = tid & 31;
    if (lane == 0) {
        wsum[wid][0] = sr;  wsum[wid][1] = sd;  wsum[wid][2] = srd;
        wsum[wid][3] = srr; wsum[wid][4] = sdd;
    }
    __syncthreads();
    if (tid == 0) {
        double a0 = 0, a1 = 0, a2 = 0, a3 = 0, a4 = 0;
        #pragma unroll
        for (int w = 0; w < 8; w++) {
            a0 += wsum[w][0]; a1 += wsum[w][1]; a2 += wsum[w][2];
            a3 += wsum[w][3]; a4 += wsum[w][4];
        }
        double* p = g_part[run * NTP2 + t];
        p[0] = a0; p[1] = a1; p[2] = a2; p[3] = a3; p[4] = a4;
    }

    // ---- last-block finalize ----
    __shared__ int isLast;
    if (tid == 0) {
        __threadfence();
        int done = atomicAdd(&g_done, 1);
        isLast = (done == TOTAL_BLOCKS - 1) ? 1 : 0;
    }
    __syncthreads();
    if (!isLast) return;

    __shared__ double red[50];
    if (tid < 50) {
        int rn = tid / 5, cp = tid % 5;
        double s = 0;
        #pragma unroll
        for (int b2 = 0; b2 < NTP2; b2++) s += g_part[rn * NTP2 + b2][cp];
        red[tid] = s;
    }
    __syncthreads();
    __shared__ double lsum[N_RUNS];
    if (tid < N_RUNS) {
        double Sr  = red[tid * 5 + 0], Sd  = red[tid * 5 + 1], Srd = red[tid * 5 + 2];
        double Srr = red[tid * 5 + 3], Sdd = red[tid * 5 + 4];
        double num = Srd - Sr * Sd / N_PAIRS;
        double den = sqrt((Srr - Sr * Sr / N_PAIRS) * (Sdd - Sd * Sd / N_PAIRS));
        lsum[tid] = (1.0 - num / den) * 0.5;
    }
    __syncthreads();
    if (tid == 0) {
        double s = 0;
        #pragma unroll
        for (int i = 0; i < N_RUNS; i++) s += lsum[i];
        out[0] = (float)(s / N_RUNS);
        g_done = 0;  // reset for next graph replay
    }
}

// ---------------------------------------------------------------------------
// Host-side JAX threefry2x32 reproduction for choice = randint(key(42),(10,),0,100)
// ---------------------------------------------------------------------------
static inline uint32_t rotl32(uint32_t x, int r) { return (x << r) | (x >> (32 - r)); }

static void threefry2x32(uint32_t k0, uint32_t k1, uint32_t c0, uint32_t c1,
                         uint32_t* o0, uint32_t* o1) {
    uint32_t ks0 = k0, ks1 = k1, ks2 = k0 ^ k1 ^ 0x1BD11BDAu;
    uint32_t x0 = c0 + ks0, x1 = c1 + ks1;
    const int rotA[4] = {13, 15, 26, 6};
    const int rotB[4] = {17, 29, 16, 24};
#define TF_ROUND4(R) do { for (int _i = 0; _i < 4; _i++) { \
        x0 += x1; x1 = rotl32(x1, (R)[_i]); x1 ^= x0; } } while (0)
    TF_ROUND4(rotA); x0 += ks1; x1 += ks2 + 1;
    TF_ROUND4(rotB); x0 += ks2; x1 += ks0 + 2;
    TF_ROUND4(rotA); x0 += ks0; x1 += ks1 + 3;
    TF_ROUND4(rotB); x0 += ks1; x1 += ks2 + 4;
    TF_ROUND4(rotA); x0 += ks2; x1 += ks0 + 5;
#undef TF_ROUND4
    *o0 = x0; *o1 = x1;
}

extern "C" void kernel_launch(void* const* d_in, const int* in_sizes, int n_in,
                              void* d_out, int out_size) {
    const float* feat = (const float*)d_in[0];
    const float* pos  = (const float*)d_in[1];
    const int*   nbh  = (const int*)d_in[2];

    uint32_t bits[N_RUNS];
    for (uint32_t i = 0; i < 5; i++) {
        uint32_t o0, o1;
        threefry2x32(0u, 42u, i, i + 5u, &o0, &o1);
        bits[i] = o0;
        bits[i + 5] = o1;
    }
    Choice ch;
    for (int i = 0; i < N_RUNS; i++) {
        uint32_t b = bits[i];
        uint32_t hi = b >> 16, lo = b & 0xFFFFu;
        ch.v[i] = (int)(((hi % 100u) * 96u + (lo % 100u)) % 100u);
    }

    prep_kernel<<<dim3(K_NBR, N_RUNS), B_FEAT>>>(feat, pos, nbh, ch);
    pair_kernel<<<dim3(NTP2, N_RUNS), 256>>>((float*)d_out);
}

// round 7
// speedup vs baseline: 1.5052x; 1.5052x over previous
#include <cuda_runtime.h>
#include <cuda_bf16.h>
#include <stdint.h>

// Problem constants
#define B_FEAT 128
#define U_UNITS 100000
#define K_NBR 500
#define N_RUNS 10
#define N_PAIRS 124750.0
#define T2 64          // pair tile edge
#define NTP2 36        // 8*9/2 lower-tri tile pairs (incl diagonal)
#define TOTAL_BLOCKS (NTP2 * N_RUNS)

// Scratch (device globals; no allocation allowed)
__device__ float  g_Y[N_RUNS][K_NBR][B_FEAT];   // normalized centered features
__device__ float2 g_P[N_RUNS][K_NBR];           // gathered positions
__device__ double g_part[TOTAL_BLOCKS][5];      // per-block partial sums
__device__ int    g_done = 0;                   // finalize counter (reset by finalizer)

struct Choice { int v[N_RUNS]; };

// ---------------------------------------------------------------------------
// Kernel 1: gather + center + normalize feature columns; gather positions
// ---------------------------------------------------------------------------
__global__ void prep_kernel(const float* __restrict__ feat,
                            const float* __restrict__ pos,
                            const int*   __restrict__ nbh,
                            Choice ch) {
    int u   = blockIdx.x;
    int run = blockIdx.y;
    int f   = threadIdx.x;
    int wid = f >> 5, lane = f & 31;

    int ind = __ldg(&nbh[ch.v[run] * K_NBR + u]);
    float v = __ldg(&feat[f * U_UNITS + ind]);

    __shared__ float ws[4];
    float s = v;
    #pragma unroll
    for (int o = 16; o > 0; o >>= 1) s += __shfl_xor_sync(0xFFFFFFFFu, s, o);
    if (lane == 0) ws[wid] = s;
    __syncthreads();
    float mean = (ws[0] + ws[1] + ws[2] + ws[3]) * (1.0f / B_FEAT);
    __syncthreads();

    float c = v - mean;
    float q = c * c;
    #pragma unroll
    for (int o = 16; o > 0; o >>= 1) q += __shfl_xor_sync(0xFFFFFFFFu, q, o);
    if (lane == 0) ws[wid] = q;
    __syncthreads();
    float inv = rsqrtf(ws[0] + ws[1] + ws[2] + ws[3]);

    g_Y[run][u][f] = c * inv;
    if (f == 0) g_P[run][u] = make_float2(__ldg(&pos[ind * 2]), __ldg(&pos[ind * 2 + 1]));
}

// ---------------------------------------------------------------------------
// Kernel 2: pair sums. 64x64 tiles, 256 threads, 4x4 micro-tile, manual
// register double-buffer over the 32 float4 feature columns (prefetch c+1
// while computing c). Column-32 prefetch hits the stride-33 padding element:
// in-bounds, unused. Single staging pass, one wave of 360 blocks.
// ---------------------------------------------------------------------------
__global__ __launch_bounds__(256) void pair_kernel(float* __restrict__ out) {
    extern __shared__ char sraw[];
    float4 (*Yi)[33] = (float4 (*)[33])sraw;
    float4 (*Yj)[33] = (float4 (*)[33])(sraw + T2 * 33 * sizeof(float4));
    float2* Pi = (float2*)(sraw + 2 * T2 * 33 * sizeof(float4));
    float2* Pj = Pi + T2;

    int run = blockIdx.y;
    int t   = blockIdx.x;
    int ti = 0;
    while ((ti + 1) * (ti + 2) / 2 <= t) ti++;
    int tj = t - ti * (ti + 1) / 2;
    int i0 = ti * T2, j0 = tj * T2;

    int tid = threadIdx.x;

    // stage tiles (each row = 32 float4 = 128 floats)
    for (int idx = tid; idx < T2 * 32; idx += 256) {
        int r = idx >> 5, c = idx & 31;
        int gi = i0 + r, gj = j0 + r;
        Yi[r][c] = (gi < K_NBR) ? ((const float4*)g_Y[run][gi])[c] : make_float4(0, 0, 0, 0);
        Yj[r][c] = (gj < K_NBR) ? ((const float4*)g_Y[run][gj])[c] : make_float4(0, 0, 0, 0);
    }
    if (tid < T2) {
        Pi[tid] = (i0 + tid < K_NBR) ? g_P[run][i0 + tid] : make_float2(0, 0);
    } else if (tid < 2 * T2) {
        int k = tid - T2;
        Pj[k] = (j0 + k < K_NBR) ? g_P[run][j0 + k] : make_float2(0, 0);
    }
    __syncthreads();

    int tx = tid & 15, ty = tid >> 4;

    float acc[4][4] = {};
    float4 af[2][4], bf[2][4];

    // preload column 0
    #pragma unroll
    for (int a = 0; a < 4; a++) af[0][a] = Yi[ty + 16 * a][0];
    #pragma unroll
    for (int b = 0; b < 4; b++) bf[0][b] = Yj[tx + 16 * b][0];

    #pragma unroll 4
    for (int c = 0; c < 32; c++) {
        int cur = c & 1, nxt = cur ^ 1;
        // prefetch next column (c=31 -> col 32 = padding, unused)
        #pragma unroll
        for (int a = 0; a < 4; a++) af[nxt][a] = Yi[ty + 16 * a][c + 1];
        #pragma unroll
        for (int b = 0; b < 4; b++) bf[nxt][b] = Yj[tx + 16 * b][c + 1];
        // compute current column
        #pragma unroll
        for (int a = 0; a < 4; a++)
            #pragma unroll
            for (int b = 0; b < 4; b++)
                acc[a][b] += af[cur][a].x * bf[cur][b].x + af[cur][a].y * bf[cur][b].y
                           + af[cur][a].z * bf[cur][b].z + af[cur][a].w * bf[cur][b].w;
    }

    float sr = 0.f, sd = 0.f, srd = 0.f, srr = 0.f, sdd = 0.f;
    #pragma unroll
    for (int a = 0; a < 4; a++) {
        int li = ty + 16 * a, gi = i0 + li;
        float2 pi = Pi[li];
        #pragma unroll
        for (int b = 0; b < 4; b++) {
            int lj = tx + 16 * b, gj = j0 + lj;
            if (gi < K_NBR && gj < K_NBR && gi > gj) {
                float dot = acc[a][b];
                float dx = pi.x - Pj[lj].x;
                float dy = pi.y - Pj[lj].y;
                float ds = 1.0f / (sqrtf(dx * dx + dy * dy) + 1.0f);
                sr  += dot;
                sd  += ds;
                srd += dot * ds;
                srr += dot * dot;
                sdd += ds * ds;
            }
        }
    }

    // block reduce 5 sums
    #pragma unroll
    for (int off = 16; off > 0; off >>= 1) {
        sr  += __shfl_down_sync(0xFFFFFFFFu, sr,  off);
        sd  += __shfl_down_sync(0xFFFFFFFFu, sd,  off);
        srd += __shfl_down_sync(0xFFFFFFFFu, srd, off);
        srr += __shfl_down_sync(0xFFFFFFFFu, srr, off);
        sdd += __shfl_down_sync(0xFFFFFFFFu, sdd, off);
    }
    __shared__ float wsum[8][5];
    int wid = tid >> 5, lane = tid & 31;
    if (lane == 0) {
        wsum[wid][0] = sr;  wsum[wid][1] = sd;  wsum[wid][2] = srd;
        wsum[wid][3] = srr; wsum[wid][4] = sdd;
    }
    __syncthreads();
    if (tid == 0) {
        double a0 = 0, a1 = 0, a2 = 0, a3 = 0, a4 = 0;
        #pragma unroll
        for (int w = 0; w < 8; w++) {
            a0 += wsum[w][0]; a1 += wsum[w][1]; a2 += wsum[w][2];
            a3 += wsum[w][3]; a4 += wsum[w][4];
        }
        double* p = g_part[run * NTP2 + t];
        p[0] = a0; p[1] = a1; p[2] = a2; p[3] = a3; p[4] = a4;
    }

    // ---- last-block finalize ----
    __shared__ int isLast;
    if (tid == 0) {
        __threadfence();
        int done = atomicAdd(&g_done, 1);
        isLast = (done == TOTAL_BLOCKS - 1) ? 1 : 0;
    }
    __syncthreads();
    if (!isLast) return;

    __shared__ double red[50];
    if (tid < 50) {
        int rn = tid / 5, cp = tid % 5;
        double s = 0;
        #pragma unroll
        for (int b2 = 0; b2 < NTP2; b2++) s += g_part[rn * NTP2 + b2][cp];
        red[tid] = s;
    }
    __syncthreads();
    __shared__ double lsum[N_RUNS];
    if (tid < N_RUNS) {
        double Sr  = red[tid * 5 + 0], Sd  = red[tid * 5 + 1], Srd = red[tid * 5 + 2];
        double Srr = red[tid * 5 + 3], Sdd = red[tid * 5 + 4];
        double num = Srd - Sr * Sd / N_PAIRS;
        double den = sqrt((Srr - Sr * Sr / N_PAIRS) * (Sdd - Sd * Sd / N_PAIRS));
        lsum[tid] = (1.0 - num / den) * 0.5;
    }
    __syncthreads();
    if (tid == 0) {
        double s = 0;
        #pragma unroll
        for (int i = 0; i < N_RUNS; i++) s += lsum[i];
        out[0] = (float)(s / N_RUNS);
        g_done = 0;  // reset for next graph replay
    }
}

// ---------------------------------------------------------------------------
// Host-side JAX threefry2x32 reproduction for choice = randint(key(42),(10,),0,100)
// ---------------------------------------------------------------------------
static inline uint32_t rotl32(uint32_t x, int r) { return (x << r) | (x >> (32 - r)); }

static void threefry2x32(uint32_t k0, uint32_t k1, uint32_t c0, uint32_t c1,
                         uint32_t* o0, uint32_t* o1) {
    uint32_t ks0 = k0, ks1 = k1, ks2 = k0 ^ k1 ^ 0x1BD11BDAu;
    uint32_t x0 = c0 + ks0, x1 = c1 + ks1;
    const int rotA[4] = {13, 15, 26, 6};
    const int rotB[4] = {17, 29, 16, 24};
#define TF_ROUND4(R) do { for (int _i = 0; _i < 4; _i++) { \
        x0 += x1; x1 = rotl32(x1, (R)[_i]); x1 ^= x0; } } while (0)
    TF_ROUND4(rotA); x0 += ks1; x1 += ks2 + 1;
    TF_ROUND4(rotB); x0 += ks2; x1 += ks0 + 2;
    TF_ROUND4(rotA); x0 += ks0; x1 += ks1 + 3;
    TF_ROUND4(rotB); x0 += ks1; x1 += ks2 + 4;
    TF_ROUND4(rotA); x0 += ks2; x1 += ks0 + 5;
#undef TF_ROUND4
    *o0 = x0; *o1 = x1;
}

extern "C" void kernel_launch(void* const* d_in, const int* in_sizes, int n_in,
                              void* d_out, int out_size) {
    const float* feat = (const float*)d_in[0];
    const float* pos  = (const float*)d_in[1];
    const int*   nbh  = (const int*)d_in[2];

    uint32_t bits[N_RUNS];
    for (uint32_t i = 0; i < 5; i++) {
        uint32_t o0, o1;
        threefry2x32(0u, 42u, i, i + 5u, &o0, &o1);
        bits[i] = o0;
        bits[i + 5] = o1;
    }
    Choice ch;
    for (int i = 0; i < N_RUNS; i++) {
        uint32_t b = bits[i];
        uint32_t hi = b >> 16, lo = b & 0xFFFFu;
        ch.v[i] = (int)(((hi % 100u) * 96u + (lo % 100u)) % 100u);
    }

    const int SMEM = 2 * T2 * 33 * (int)sizeof(float4) + 2 * T2 * (int)sizeof(float2);
    cudaFuncSetAttribute(pair_kernel, cudaFuncAttributeMaxDynamicSharedMemorySize, SMEM);

    prep_kernel<<<dim3(K_NBR, N_RUNS), B_FEAT>>>(feat, pos, nbh, ch);
    pair_kernel<<<dim3(NTP2, N_RUNS), 256, SMEM>>>((float*)d_out);
}